// round 5
// baseline (speedup 1.0000x reference)
#include <cuda_runtime.h>

#define Bq 32
#define Tq 512
#define Hq 512
#define FFq 2048

typedef unsigned long long u64;

// ---------------- static device scratch ---------------------------------------
__device__ float g_Uf[Bq*Tq*Hq];
__device__ float g_Ub[Bq*Tq*Hq];
__device__ float g_Z [Bq*Tq*2*Hq];
__device__ float g_A [Bq*Tq*FFq];
__device__ float g_h [2*2*Bq*Hq];       // [dir][pingpong][b*H+j]
__device__ float g_S [Bq*2*Hq];
__device__ float g_As[Bq*FFq];
__device__ unsigned g_bar2[64];          // per-dir counters, 128B apart

__device__ __forceinline__ u64 pk2(float lo, float hi) {
    u64 r; asm("mov.b64 %0, {%1, %2};" : "=l"(r) : "f"(lo), "f"(hi)); return r;
}
__device__ __forceinline__ void fma2(u64& d, u64 a, u64 b) {
    asm("fma.rn.f32x2 %0, %1, %2, %0;" : "+l"(d) : "l"(a), "l"(b));
}
__device__ __forceinline__ void addf2(u64& d, u64 a) {
    asm("add.rn.f32x2 %0, %0, %1;" : "+l"(d) : "l"(a));
}
__device__ __forceinline__ float2 upk(u64 v) {
    float2 f; asm("mov.b64 {%0, %1}, %2;" : "=f"(f.x), "=f"(f.y) : "l"(v)); return f;
}

// ---------------- init ---------------------------------------------------------
__global__ void init_kernel() {
    size_t idx = (size_t)blockIdx.x * blockDim.x + threadIdx.x;
    size_t stride = (size_t)gridDim.x * blockDim.x;
    float4 z = make_float4(0.f, 0.f, 0.f, 0.f);
    for (size_t i = idx; i < (size_t)(Bq*Tq*2*Hq)/4; i += stride) ((float4*)g_Z)[i] = z;
    for (size_t i = idx; i < (size_t)(2*2*Bq*Hq)/4; i += stride) ((float4*)g_h)[i] = z;
    if (idx < 64) g_bar2[idx] = 0u;
}

// ---------------- 128x128x16 fp32 GEMM via packed f32x2 -------------------------
__global__ void __launch_bounds__(256, 2) gemm_kernel(
    const float* __restrict__ A, const float* __restrict__ B,
    const float* __restrict__ bias, float* __restrict__ C,
    int M, int N, int K, int act)
{
    __shared__ u64   As_u[16*128];
    __shared__ float Bs[16*128];

    const int tid = threadIdx.x;
    const int bn = blockIdx.x, bm = blockIdx.y;
    const int tx = tid & 15, ty = tid >> 4;

    u64 acc[8][4];
    #pragma unroll
    for (int i = 0; i < 8; ++i)
        #pragma unroll
        for (int p = 0; p < 4; ++p) acc[i][p] = 0ull;

    const int arow = tid >> 1;
    const int acol = (tid & 1) * 8;
    const int brow = tid >> 4;
    const int grow = bm * 128 + arow;
    const bool aok = grow < M;
    const float* Ap = A + (size_t)grow * K + acol;
    const float* Bp = B + (size_t)brow * N + bn * 128 + tx * 8;

    float4 a0 = make_float4(0.f,0.f,0.f,0.f), a1 = a0;
    if (aok) { a0 = *(const float4*)(Ap); a1 = *(const float4*)(Ap + 4); }
    float4 b0 = *(const float4*)(Bp);
    float4 b1 = *(const float4*)(Bp + 4);

    for (int k0 = 0; k0 < K; k0 += 16) {
        __syncthreads();
        As_u[(acol + 0)*128 + arow] = pk2(a0.x, a0.x);
        As_u[(acol + 1)*128 + arow] = pk2(a0.y, a0.y);
        As_u[(acol + 2)*128 + arow] = pk2(a0.z, a0.z);
        As_u[(acol + 3)*128 + arow] = pk2(a0.w, a0.w);
        As_u[(acol + 4)*128 + arow] = pk2(a1.x, a1.x);
        As_u[(acol + 5)*128 + arow] = pk2(a1.y, a1.y);
        As_u[(acol + 6)*128 + arow] = pk2(a1.z, a1.z);
        As_u[(acol + 7)*128 + arow] = pk2(a1.w, a1.w);
        *(float4*)&Bs[brow*128 + tx*4]      = b0;
        *(float4*)&Bs[brow*128 + 64 + tx*4] = b1;
        __syncthreads();

        if (k0 + 16 < K) {
            if (aok) {
                a0 = *(const float4*)(Ap + k0 + 16);
                a1 = *(const float4*)(Ap + k0 + 20);
            }
            b0 = *(const float4*)(Bp + (size_t)(k0 + 16) * N);
            b1 = *(const float4*)(Bp + (size_t)(k0 + 16) * N + 4);
        }

        #pragma unroll
        for (int kk = 0; kk < 16; ++kk) {
            const u64* ap = &As_u[kk*128 + ty*8];
            ulonglong2 av0 = *(const ulonglong2*)(ap + 0);
            ulonglong2 av1 = *(const ulonglong2*)(ap + 2);
            ulonglong2 av2 = *(const ulonglong2*)(ap + 4);
            ulonglong2 av3 = *(const ulonglong2*)(ap + 6);
            ulonglong2 bv0 = *(const ulonglong2*)&Bs[kk*128 + tx*4];
            ulonglong2 bv1 = *(const ulonglong2*)&Bs[kk*128 + 64 + tx*4];
            u64 aa[8] = {av0.x, av0.y, av1.x, av1.y, av2.x, av2.y, av3.x, av3.y};
            u64 bb[4] = {bv0.x, bv0.y, bv1.x, bv1.y};
            #pragma unroll
            for (int i = 0; i < 8; ++i)
                #pragma unroll
                for (int p = 0; p < 4; ++p)
                    fma2(acc[i][p], aa[i], bb[p]);
        }
    }

    const int gcol = bn * 128 + tx * 8;
    float bv[8];
    #pragma unroll
    for (int p = 0; p < 4; ++p) {
        float2 t = *(const float2*)&bias[gcol + 2 * p];
        bv[2*p] = t.x; bv[2*p+1] = t.y;
    }
    #pragma unroll
    for (int i = 0; i < 8; ++i) {
        int row = bm * 128 + ty * 8 + i;
        if (row < M) {
            float o[8];
            #pragma unroll
            for (int p = 0; p < 4; ++p) {
                float2 v = upk(acc[i][p]);
                o[2*p]   = v.x + bv[2*p];
                o[2*p+1] = v.y + bv[2*p+1];
            }
            if (act) {
                #pragma unroll
                for (int c = 0; c < 8; ++c) o[c] = tanhf(o[c]);
            }
            *(float4*)&C[(size_t)row * N + gcol]     = make_float4(o[0],o[1],o[2],o[3]);
            *(float4*)&C[(size_t)row * N + gcol + 4] = make_float4(o[4],o[5],o[6],o[7]);
        }
    }
}

// ---------------- persistent bidirectional RNN ---------------------------------
// 128 CTAs (64/dir) x 256 threads. CTA owns 8 j-cols. Thread = (wid, ks, bi):
// tile 4b x 8j(4 pairs) x 16k. h staged coalesced to swizzled smem; W packed as
// j-pairs; partials reduced via padded smem with add.f32x2; per-dir barrier.
#define SM_H    0                 // 16384 floats (float4[32][128], swizzled)
#define SM_W    16384             // 2048 u64 (4096 floats)
#define SM_RED  20480             // 4128 u64 (8256 floats)
#define SM_TOT  ((20480 + 8256) * 4)

__global__ void __launch_bounds__(256, 1) rnn_kernel(
    const int* __restrict__ length,
    const float* __restrict__ Wf_h, const float* __restrict__ Wb_h)
{
    extern __shared__ float sm[];
    float4* h_s4  = (float4*)(sm + SM_H);      // [b*128 + (c4 ^ ((b>>2)&7))]
    u64*    Wps   = (u64*)  (sm + SM_W);       // [k*4 + jp]
    u64*    red   = (u64*)  (sm + SM_RED);     // [b*129 + jp*32 + wid*4 + ks]

    const int tid  = threadIdx.x;
    const int wid  = tid >> 5;
    const int lane = tid & 31;
    const int bi   = lane & 7;
    const int ks   = lane >> 3;
    const int dir  = blockIdx.x >> 6;
    const int j0   = (blockIdx.x & 63) * 8;
    const float* W = dir ? Wb_h : Wf_h;
    const float* U = dir ? g_Ub : g_Uf;
    float* hbase   = g_h + dir * 2 * (Bq*Hq);
    unsigned* bar  = &g_bar2[dir * 32];

    // pack W j-pairs: Wps[k][jp] = (W[k][j0+2jp], W[k][j0+2jp+1])
    for (int i = tid; i < 2048; i += 256) {
        int k = i >> 2, jp = i & 3;
        float2 w = *(const float2*)&W[k * Hq + j0 + 2 * jp];
        Wps[i] = pk2(w.x, w.y);
    }

    // final-reduce thread identity
    const int rb = tid >> 2;          // 0..31 (valid for tid<128)
    const int rjp = tid & 3;
    const int Lb = length[rb & 31];
    float2 hp = make_float2(0.f, 0.f);

    const int c4base = wid * 16 + ks * 4;
    const int rowA = bi * 4;
    __syncthreads();

    for (int s = 0; s < Tq; ++s) {
        const float* hin = hbase + (s & 1) * (Bq*Hq);
        float* hout      = hbase + ((s + 1) & 1) * (Bq*Hq);

        // ---- stage h: coalesced LDG.128 -> swizzled smem
        #pragma unroll
        for (int it = 0; it < 16; ++it) {
            int f = tid + it * 256;
            int b = f >> 7, c4 = f & 127;
            h_s4[b * 128 + (c4 ^ ((b >> 2) & 7))] = __ldcg((const float4*)hin + f);
        }
        __syncthreads();

        // ---- compute partial dots
        u64 acc[4][4];
        #pragma unroll
        for (int ib = 0; ib < 4; ++ib)
            #pragma unroll
            for (int jp = 0; jp < 4; ++jp) acc[ib][jp] = 0ull;

        #pragma unroll
        for (int it = 0; it < 4; ++it) {
            float hv[4][4];
            #pragma unroll
            for (int ib = 0; ib < 4; ++ib)
                *(float4*)hv[ib] = h_s4[(rowA + ib) * 128 + ((c4base + it) ^ bi)];
            int kb = (wid * 64 + ks * 16 + it * 4) * 4;
            ulonglong2 w0 = *(const ulonglong2*)&Wps[kb + 0];
            ulonglong2 w1 = *(const ulonglong2*)&Wps[kb + 2];
            ulonglong2 w2 = *(const ulonglong2*)&Wps[kb + 4];
            ulonglong2 w3 = *(const ulonglong2*)&Wps[kb + 6];
            ulonglong2 w4 = *(const ulonglong2*)&Wps[kb + 8];
            ulonglong2 w5 = *(const ulonglong2*)&Wps[kb + 10];
            ulonglong2 w6 = *(const ulonglong2*)&Wps[kb + 12];
            ulonglong2 w7 = *(const ulonglong2*)&Wps[kb + 14];
            u64 wv[4][4] = {
                {w0.x, w0.y, w1.x, w1.y}, {w2.x, w2.y, w3.x, w3.y},
                {w4.x, w4.y, w5.x, w5.y}, {w6.x, w6.y, w7.x, w7.y}};
            #pragma unroll
            for (int kk = 0; kk < 4; ++kk)
                #pragma unroll
                for (int ib = 0; ib < 4; ++ib) {
                    u64 hd = pk2(hv[ib][kk], hv[ib][kk]);
                    #pragma unroll
                    for (int jp = 0; jp < 4; ++jp)
                        fma2(acc[ib][jp], hd, wv[kk][jp]);
                }
        }

        // ---- write partials
        #pragma unroll
        for (int ib = 0; ib < 4; ++ib)
            #pragma unroll
            for (int jp = 0; jp < 4; ++jp)
                red[(rowA + ib) * 129 + jp * 32 + wid * 4 + ks] = acc[ib][jp];
        __syncthreads();

        // ---- final reduce + update (threads 0..127)
        if (tid < 128) {
            u64 sum2 = 0ull;
            const u64* rp = &red[rb * 129 + rjp * 32];
            #pragma unroll
            for (int w8 = 0; w8 < 32; ++w8) addf2(sum2, rp[w8]);
            float2 p = upk(sum2);

            float2 hn;
            if (s < Lb) {
                int t = dir ? (Lb - 1 - s) : s;
                const float2 u = *(const float2*)&U[((size_t)(rb * Tq + t)) * Hq + j0 + 2 * rjp];
                hn.x = tanhf(u.x + p.x);
                hn.y = tanhf(u.y + p.y);
                *(float2*)&g_Z[((size_t)(rb * Tq + t)) * (2*Hq) + dir * Hq + j0 + 2 * rjp] = hn;
            } else {
                hn = hp;
            }
            hp = hn;
            *(float2*)&hout[rb * Hq + j0 + 2 * rjp] = hn;
        }

        // ---- per-direction grid barrier
        __syncthreads();
        if (tid == 0) {
            asm volatile("red.release.gpu.global.add.u32 [%0], 1;" :: "l"(bar) : "memory");
            unsigned tgt = (unsigned)(s + 1) * 64u;
            unsigned v;
            do {
                asm volatile("ld.acquire.gpu.u32 %0, [%1];" : "=r"(v) : "l"(bar));
            } while (v < tgt);
        }
        __syncthreads();
    }
}

// ---------------- states assembly ----------------------------------------------
__global__ void states_kernel() {
    int i = blockIdx.x * blockDim.x + threadIdx.x;
    if (i < Bq * 2 * Hq) {
        int b = i >> 10, c = i & 1023;
        int dir = c >> 9, j = c & 511;
        g_S[i] = g_h[dir * 2 * (Bq*Hq) + b * Hq + j];   // final h in pingpong buf 0
    }
}

// ---------------- launcher ------------------------------------------------------
extern "C" void kernel_launch(void* const* d_in, const int* in_sizes, int n_in,
                              void* d_out, int out_size) {
    const float* x      = (const float*)d_in[0];
    const int*   length = (const int*)  d_in[1];
    const float* Wf     = (const float*)d_in[2];
    const float* bf     = (const float*)d_in[3];
    const float* Wb     = (const float*)d_in[4];
    const float* bb     = (const float*)d_in[5];
    const float* W1     = (const float*)d_in[6];
    const float* b1     = (const float*)d_in[7];
    const float* W2     = (const float*)d_in[8];
    const float* b2     = (const float*)d_in[9];
    float* out = (float*)d_out;

    void *pUf, *pUb, *pZ, *pA, *pS, *pAs;
    cudaGetSymbolAddress(&pUf, g_Uf);
    cudaGetSymbolAddress(&pUb, g_Ub);
    cudaGetSymbolAddress(&pZ,  g_Z);
    cudaGetSymbolAddress(&pA,  g_A);
    cudaGetSymbolAddress(&pS,  g_S);
    cudaGetSymbolAddress(&pAs, g_As);

    cudaFuncSetAttribute(rnn_kernel, cudaFuncAttributeMaxDynamicSharedMemorySize, SM_TOT);

    const int M = Bq * Tq;   // 16384

    init_kernel<<<2048, 256>>>();

    gemm_kernel<<<dim3(Hq/128, M/128), 256>>>(x, Wf, bf, (float*)pUf, M, Hq, Hq, 0);
    gemm_kernel<<<dim3(Hq/128, M/128), 256>>>(x, Wb, bb, (float*)pUb, M, Hq, Hq, 0);

    rnn_kernel<<<128, 256, SM_TOT>>>(length, Wf + Hq*Hq, Wb + Hq*Hq);

    gemm_kernel<<<dim3(FFq/128, M/128), 256>>>((const float*)pZ, W1, b1, (float*)pA, M, FFq, 2*Hq, 1);
    gemm_kernel<<<dim3((2*Hq)/128, M/128), 256>>>((const float*)pA, W2, b2, out, M, 2*Hq, FFq, 0);

    states_kernel<<<(Bq*2*Hq + 255)/256, 256>>>();
    gemm_kernel<<<dim3(FFq/128, 1), 256>>>((const float*)pS, W1, b1, (float*)pAs, Bq, FFq, 2*Hq, 1);
    gemm_kernel<<<dim3((2*Hq)/128, 1), 256>>>((const float*)pAs, W2, b2, out + (size_t)M * 2 * Hq, Bq, 2*Hq, FFq, 0);
}

// round 6
// speedup vs baseline: 1.9630x; 1.9630x over previous
#include <cuda_runtime.h>

#define Bq 32
#define Tq 512
#define Hq 512
#define FFq 2048

typedef unsigned long long u64;
typedef unsigned int u32;

// ---------------- static device scratch ---------------------------------------
__device__ float g_Uf[Bq*Tq*Hq];
__device__ float g_Ub[Bq*Tq*Hq];
__device__ float g_Z [Bq*Tq*2*Hq];
__device__ float g_A [Bq*Tq*FFq];
__device__ float g_h [2*2*Bq*Hq];       // [dir][pingpong][b*H+j]
__device__ float g_S [Bq*2*Hq];
__device__ float g_As[Bq*FFq];
__device__ unsigned g_bar;

__device__ __forceinline__ u64 pk2(float lo, float hi) {
    u64 r; asm("mov.b64 %0, {%1, %2};" : "=l"(r) : "f"(lo), "f"(hi)); return r;
}
__device__ __forceinline__ void fma2(u64& d, u64 a, u64 b) {
    asm("fma.rn.f32x2 %0, %1, %2, %0;" : "+l"(d) : "l"(a), "l"(b));
}
__device__ __forceinline__ float2 upk(u64 v) {
    float2 f; asm("mov.b64 {%0, %1}, %2;" : "=f"(f.x), "=f"(f.y) : "l"(v)); return f;
}
__device__ __forceinline__ u32 f2tf32(float f) {
    u32 r; asm("cvt.rna.tf32.f32 %0, %1;" : "=r"(r) : "f"(f)); return r;
}

// ---------------- init ---------------------------------------------------------
__global__ void init_kernel() {
    size_t idx = (size_t)blockIdx.x * blockDim.x + threadIdx.x;
    size_t stride = (size_t)gridDim.x * blockDim.x;
    float4 z = make_float4(0.f, 0.f, 0.f, 0.f);
    for (size_t i = idx; i < (size_t)(Bq*Tq*2*Hq)/4; i += stride) ((float4*)g_Z)[i] = z;
    for (size_t i = idx; i < (size_t)(2*2*Bq*Hq)/4; i += stride) ((float4*)g_h)[i] = z;
    if (idx == 0) g_bar = 0u;
}

// ---------------- TF32 tensor-core GEMM: 128x128 tile, k-chunk 32 ---------------
// C[M,N] = op(A[M,K] @ B[K,N] + bias[N]); act -> tanh. N%128==0, K%32==0.
// A staged transposed to smem [k][m], B as [k][n], both stride 132 (tf32 bits).
// Warps 4(M)x2(N); warp tile 32x64 via m16n8k8 atoms.
#define MMA_TF32(d, a, b0, b1)                                                  \
    asm volatile("mma.sync.aligned.m16n8k8.row.col.f32.tf32.tf32.f32 "          \
        "{%0,%1,%2,%3}, {%4,%5,%6,%7}, {%8,%9}, {%0,%1,%2,%3};"                 \
        : "+f"(d[0]), "+f"(d[1]), "+f"(d[2]), "+f"(d[3])                        \
        : "r"(a[0]), "r"(a[1]), "r"(a[2]), "r"(a[3]), "r"(b0), "r"(b1))

__global__ void __launch_bounds__(256, 2) gemm_tc(
    const float* __restrict__ A, const float* __restrict__ B,
    const float* __restrict__ bias, float* __restrict__ C,
    int M, int N, int K, int act)
{
    __shared__ u32 As_t[32*132];   // [k][m]
    __shared__ u32 Bs  [32*132];   // [k][n]

    const int tid  = threadIdx.x;
    const int wid  = tid >> 5;
    const int lane = tid & 31;
    const int g    = lane >> 2;
    const int t4   = lane & 3;
    const int bn = blockIdx.x, bm = blockIdx.y;
    const int warpM = (wid & 3) * 32;
    const int warpN = (wid >> 2) * 64;

    float acc[2][8][4];
    #pragma unroll
    for (int ma = 0; ma < 2; ++ma)
        #pragma unroll
        for (int na = 0; na < 8; ++na)
            #pragma unroll
            for (int c = 0; c < 4; ++c) acc[ma][na][c] = 0.f;

    // staging identities
    const int arow = tid >> 1;            // 0..127
    const int akb  = (tid & 1) * 16;      // 0 / 16
    const int brow = tid >> 3;            // 0..31
    const int bcg  = (tid & 7) * 16;      // 0..112
    const int grow = bm * 128 + arow;
    const bool aok = grow < M;
    const float* Ap = A + (size_t)grow * K + akb;
    const float* Bp = B + (size_t)brow * N + bn * 128 + bcg;

    float4 pa[4], pb[4];
    #pragma unroll
    for (int q = 0; q < 4; ++q) {
        pa[q] = aok ? *(const float4*)(Ap + 4*q) : make_float4(0.f,0.f,0.f,0.f);
        pb[q] = *(const float4*)(Bp + 4*q);
    }

    for (int k0 = 0; k0 < K; k0 += 32) {
        __syncthreads();
        #pragma unroll
        for (int q = 0; q < 4; ++q) {
            const float* e = (const float*)&pa[q];
            #pragma unroll
            for (int c = 0; c < 4; ++c)
                As_t[(akb + 4*q + c)*132 + arow] = f2tf32(e[c]);
            const float* f = (const float*)&pb[q];
            #pragma unroll
            for (int c = 0; c < 4; ++c)
                Bs[brow*132 + bcg + 4*q + c] = f2tf32(f[c]);
        }
        __syncthreads();

        if (k0 + 32 < K) {
            #pragma unroll
            for (int q = 0; q < 4; ++q) {
                pa[q] = aok ? *(const float4*)(Ap + k0 + 32 + 4*q)
                            : make_float4(0.f,0.f,0.f,0.f);
                pb[q] = *(const float4*)(Bp + (size_t)(k0 + 32) * N + 4*q);
            }
        }

        #pragma unroll
        for (int kk = 0; kk < 4; ++kk) {
            const int kof = kk * 8;
            u32 afr[2][4];
            const int ab = (kof + t4)*132 + warpM + g;
            #pragma unroll
            for (int ma = 0; ma < 2; ++ma) {
                afr[ma][0] = As_t[ab + ma*16];
                afr[ma][1] = As_t[ab + ma*16 + 8];
                afr[ma][2] = As_t[ab + ma*16 + 4*132];
                afr[ma][3] = As_t[ab + ma*16 + 8 + 4*132];
            }
            const int bb = (kof + t4)*132 + warpN + g;
            #pragma unroll
            for (int na = 0; na < 8; ++na) {
                u32 b0 = Bs[bb + na*8];
                u32 b1 = Bs[bb + na*8 + 4*132];
                MMA_TF32(acc[0][na], afr[0], b0, b1);
                MMA_TF32(acc[1][na], afr[1], b0, b1);
            }
        }
    }

    // epilogue
    #pragma unroll
    for (int na = 0; na < 8; ++na) {
        const int col = bn * 128 + warpN + na*8 + 2*t4;
        const float2 bv = *(const float2*)&bias[col];
        #pragma unroll
        for (int ma = 0; ma < 2; ++ma) {
            const int r0 = bm * 128 + warpM + ma*16 + g;
            float o0 = acc[ma][na][0] + bv.x;
            float o1 = acc[ma][na][1] + bv.y;
            float o2 = acc[ma][na][2] + bv.x;
            float o3 = acc[ma][na][3] + bv.y;
            if (act) { o0 = tanhf(o0); o1 = tanhf(o1); o2 = tanhf(o2); o3 = tanhf(o3); }
            if (r0 < M)     *(float2*)&C[(size_t)r0 * N + col]       = make_float2(o0, o1);
            if (r0 + 8 < M) *(float2*)&C[(size_t)(r0 + 8) * N + col] = make_float2(o2, o3);
        }
    }
}

// ---------------- persistent bidirectional RNN (reverted to 6549us version) ----
// 128 CTAs x 256 threads. CTA = (dir, 8 j-columns). Warp w handles k-slice
// [w*64, w*64+64). Lane = (bi 0..7, ji 0..3); thread tile = 4 b x 2 j.
// h read directly from L2 (__ldcg), Wh slice in smem, cross-warp smem reduce.
__global__ void __launch_bounds__(256, 1) rnn_kernel(
    const int* __restrict__ length,
    const float* __restrict__ Wf_h, const float* __restrict__ Wb_h)
{
    __shared__ float Whs[8 * 516];     // [jl][k], stride 516
    __shared__ float red[8 * 288];     // [warp][b*9 + jl]

    const int tid  = threadIdx.x;
    const int wid  = tid >> 5;
    const int lane = tid & 31;
    const int bi   = lane >> 2;
    const int ji   = lane & 3;
    const int dir  = blockIdx.x >> 6;
    const int j0   = (blockIdx.x & 63) * 8;
    const float* W = dir ? Wb_h : Wf_h;
    const float* U = dir ? g_Ub : g_Uf;
    float* hbase   = g_h + dir * 2 * (Bq*Hq);

    const int rb = tid >> 3;
    const int rj = tid & 7;
    const int L  = length[rb];
    float hprev = 0.f;

    for (int i = tid; i < 8 * Hq; i += 256) {
        int kk = i >> 3, jj = i & 7;
        Whs[jj * 516 + kk] = W[kk * Hq + j0 + jj];
    }

    const int k0 = wid * 64;
    const int bA = bi * 4;
    __syncthreads();

    for (int s = 0; s < Tq; ++s) {
        const float* hin = hbase + (s & 1) * (Bq*Hq);
        float* hout      = hbase + ((s + 1) & 1) * (Bq*Hq);

        u64 acc[4][2];
        #pragma unroll
        for (int ib = 0; ib < 4; ++ib) { acc[ib][0] = 0ull; acc[ib][1] = 0ull; }

        #pragma unroll 8
        for (int it = 0; it < 16; ++it) {
            int k = k0 + it * 4;
            float4 h0 = __ldcg((const float4*)(hin + (bA + 0) * Hq + k));
            float4 h1 = __ldcg((const float4*)(hin + (bA + 1) * Hq + k));
            float4 h2 = __ldcg((const float4*)(hin + (bA + 2) * Hq + k));
            float4 h3 = __ldcg((const float4*)(hin + (bA + 3) * Hq + k));
            ulonglong2 wA = *(const ulonglong2*)&Whs[(ji * 2 + 0) * 516 + k];
            ulonglong2 wB = *(const ulonglong2*)&Whs[(ji * 2 + 1) * 516 + k];
            const ulonglong2* hv;
            hv = (const ulonglong2*)&h0;
            fma2(acc[0][0], hv->x, wA.x); fma2(acc[0][0], hv->y, wA.y);
            fma2(acc[0][1], hv->x, wB.x); fma2(acc[0][1], hv->y, wB.y);
            hv = (const ulonglong2*)&h1;
            fma2(acc[1][0], hv->x, wA.x); fma2(acc[1][0], hv->y, wA.y);
            fma2(acc[1][1], hv->x, wB.x); fma2(acc[1][1], hv->y, wB.y);
            hv = (const ulonglong2*)&h2;
            fma2(acc[2][0], hv->x, wA.x); fma2(acc[2][0], hv->y, wA.y);
            fma2(acc[2][1], hv->x, wB.x); fma2(acc[2][1], hv->y, wB.y);
            hv = (const ulonglong2*)&h3;
            fma2(acc[3][0], hv->x, wA.x); fma2(acc[3][0], hv->y, wA.y);
            fma2(acc[3][1], hv->x, wB.x); fma2(acc[3][1], hv->y, wB.y);
        }

        #pragma unroll
        for (int ib = 0; ib < 4; ++ib)
            #pragma unroll
            for (int ij = 0; ij < 2; ++ij) {
                float2 p = upk(acc[ib][ij]);
                red[wid * 288 + (bA + ib) * 9 + (ji * 2 + ij)] = p.x + p.y;
            }
        __syncthreads();

        float dot = 0.f;
        #pragma unroll
        for (int w = 0; w < 8; ++w) dot += red[w * 288 + rb * 9 + rj];

        float hnew;
        if (s < L) {
            int t = dir ? (L - 1 - s) : s;
            float u = U[((size_t)(rb * Tq + t)) * Hq + j0 + rj];
            hnew = tanhf(u + dot);
            g_Z[((size_t)(rb * Tq + t)) * (2*Hq) + dir * Hq + j0 + rj] = hnew;
        } else {
            hnew = hprev;
        }
        hprev = hnew;
        hout[rb * Hq + j0 + rj] = hnew;

        __threadfence();
        __syncthreads();
        if (tid == 0) {
            atomicAdd(&g_bar, 1u);
            unsigned tgt = (unsigned)(s + 1) * 128u;
            unsigned v;
            do {
                asm volatile("ld.acquire.gpu.u32 %0, [%1];" : "=r"(v) : "l"(&g_bar));
            } while (v < tgt);
        }
        __syncthreads();
    }
}

// ---------------- states assembly ----------------------------------------------
__global__ void states_kernel() {
    int i = blockIdx.x * blockDim.x + threadIdx.x;
    if (i < Bq * 2 * Hq) {
        int b = i >> 10, c = i & 1023;
        int dir = c >> 9, j = c & 511;
        g_S[i] = g_h[dir * 2 * (Bq*Hq) + b * Hq + j];   // final h in pingpong buf 0
    }
}

// ---------------- launcher ------------------------------------------------------
extern "C" void kernel_launch(void* const* d_in, const int* in_sizes, int n_in,
                              void* d_out, int out_size) {
    const float* x      = (const float*)d_in[0];
    const int*   length = (const int*)  d_in[1];
    const float* Wf     = (const float*)d_in[2];
    const float* bf     = (const float*)d_in[3];
    const float* Wb     = (const float*)d_in[4];
    const float* bb     = (const float*)d_in[5];
    const float* W1     = (const float*)d_in[6];
    const float* b1     = (const float*)d_in[7];
    const float* W2     = (const float*)d_in[8];
    const float* b2     = (const float*)d_in[9];
    float* out = (float*)d_out;

    void *pUf, *pUb, *pZ, *pA, *pS, *pAs;
    cudaGetSymbolAddress(&pUf, g_Uf);
    cudaGetSymbolAddress(&pUb, g_Ub);
    cudaGetSymbolAddress(&pZ,  g_Z);
    cudaGetSymbolAddress(&pA,  g_A);
    cudaGetSymbolAddress(&pS,  g_S);
    cudaGetSymbolAddress(&pAs, g_As);

    const int M = Bq * Tq;   // 16384

    init_kernel<<<2048, 256>>>();

    gemm_tc<<<dim3(Hq/128, M/128), 256>>>(x, Wf, bf, (float*)pUf, M, Hq, Hq, 0);
    gemm_tc<<<dim3(Hq/128, M/128), 256>>>(x, Wb, bb, (float*)pUb, M, Hq, Hq, 0);

    rnn_kernel<<<128, 256>>>(length, Wf + Hq*Hq, Wb + Hq*Hq);

    gemm_tc<<<dim3(FFq/128, M/128), 256>>>((const float*)pZ, W1, b1, (float*)pA, M, FFq, 2*Hq, 1);
    gemm_tc<<<dim3((2*Hq)/128, M/128), 256>>>((const float*)pA, W2, b2, out, M, 2*Hq, FFq, 0);

    states_kernel<<<(Bq*2*Hq + 255)/256, 256>>>();
    gemm_tc<<<dim3(FFq/128, 1), 256>>>((const float*)pS, W1, b1, (float*)pAs, Bq, FFq, 2*Hq, 1);
    gemm_tc<<<dim3((2*Hq)/128, 1), 256>>>((const float*)pAs, W2, b2, out + (size_t)M * 2 * Hq, Bq, 2*Hq, FFq, 0);
}

// round 7
// speedup vs baseline: 2.2634x; 1.1531x over previous
#include <cuda_runtime.h>

#define Bq 32
#define Tq 512
#define Hq 512
#define FFq 2048

typedef unsigned long long u64;
typedef unsigned int u32;

// ---------------- static device scratch ---------------------------------------
__device__ float g_Uf[Bq*Tq*Hq];
__device__ float g_Ub[Bq*Tq*Hq];
__device__ float g_Z [Bq*Tq*2*Hq];
__device__ float g_A [Bq*Tq*FFq];
__device__ float g_h [2*2*Bq*Hq];       // [dir][pingpong][b*H+j]
__device__ float g_S [Bq*2*Hq];
__device__ float g_As[Bq*FFq];
__device__ unsigned g_bar2[64];          // per-dir counters, 128B apart

__device__ __forceinline__ u64 pk2(float lo, float hi) {
    u64 r; asm("mov.b64 %0, {%1, %2};" : "=l"(r) : "f"(lo), "f"(hi)); return r;
}
__device__ __forceinline__ void fma2(u64& d, u64 a, u64 b) {
    asm("fma.rn.f32x2 %0, %1, %2, %0;" : "+l"(d) : "l"(a), "l"(b));
}
__device__ __forceinline__ float2 upk(u64 v) {
    float2 f; asm("mov.b64 {%0, %1}, %2;" : "=f"(f.x), "=f"(f.y) : "l"(v)); return f;
}
__device__ __forceinline__ u32 f2tf32(float f) {
    u32 r; asm("cvt.rna.tf32.f32 %0, %1;" : "=r"(r) : "f"(f)); return r;
}

// ---------------- init ---------------------------------------------------------
__global__ void init_kernel() {
    size_t idx = (size_t)blockIdx.x * blockDim.x + threadIdx.x;
    size_t stride = (size_t)gridDim.x * blockDim.x;
    float4 z = make_float4(0.f, 0.f, 0.f, 0.f);
    for (size_t i = idx; i < (size_t)(Bq*Tq*2*Hq)/4; i += stride) ((float4*)g_Z)[i] = z;
    for (size_t i = idx; i < (size_t)(2*2*Bq*Hq)/4; i += stride) ((float4*)g_h)[i] = z;
    if (idx < 64) g_bar2[idx] = 0u;
}

// ---------------- TF32 tensor-core GEMM: 128x128 tile, k-chunk 32 ---------------
#define MMA_TF32(d, a, b0, b1)                                                  \
    asm volatile("mma.sync.aligned.m16n8k8.row.col.f32.tf32.tf32.f32 "          \
        "{%0,%1,%2,%3}, {%4,%5,%6,%7}, {%8,%9}, {%0,%1,%2,%3};"                 \
        : "+f"(d[0]), "+f"(d[1]), "+f"(d[2]), "+f"(d[3])                        \
        : "r"(a[0]), "r"(a[1]), "r"(a[2]), "r"(a[3]), "r"(b0), "r"(b1))

__global__ void __launch_bounds__(256, 2) gemm_tc(
    const float* __restrict__ A, const float* __restrict__ B,
    const float* __restrict__ bias, float* __restrict__ C,
    int M, int N, int K, int act)
{
    __shared__ u32 As_t[32*132];   // [k][m]
    __shared__ u32 Bs  [32*132];   // [k][n]

    const int tid  = threadIdx.x;
    const int wid  = tid >> 5;
    const int lane = tid & 31;
    const int g    = lane >> 2;
    const int t4   = lane & 3;
    const int bn = blockIdx.x, bm = blockIdx.y;
    const int warpM = (wid & 3) * 32;
    const int warpN = (wid >> 2) * 64;

    float acc[2][8][4];
    #pragma unroll
    for (int ma = 0; ma < 2; ++ma)
        #pragma unroll
        for (int na = 0; na < 8; ++na)
            #pragma unroll
            for (int c = 0; c < 4; ++c) acc[ma][na][c] = 0.f;

    const int arow = tid >> 1;
    const int akb  = (tid & 1) * 16;
    const int brow = tid >> 3;
    const int bcg  = (tid & 7) * 16;
    const int grow = bm * 128 + arow;
    const bool aok = grow < M;
    const float* Ap = A + (size_t)grow * K + akb;
    const float* Bp = B + (size_t)brow * N + bn * 128 + bcg;

    float4 pa[4], pb[4];
    #pragma unroll
    for (int q = 0; q < 4; ++q) {
        pa[q] = aok ? *(const float4*)(Ap + 4*q) : make_float4(0.f,0.f,0.f,0.f);
        pb[q] = *(const float4*)(Bp + 4*q);
    }

    for (int k0 = 0; k0 < K; k0 += 32) {
        __syncthreads();
        #pragma unroll
        for (int q = 0; q < 4; ++q) {
            const float* e = (const float*)&pa[q];
            #pragma unroll
            for (int c = 0; c < 4; ++c)
                As_t[(akb + 4*q + c)*132 + arow] = f2tf32(e[c]);
            const float* f = (const float*)&pb[q];
            #pragma unroll
            for (int c = 0; c < 4; ++c)
                Bs[brow*132 + bcg + 4*q + c] = f2tf32(f[c]);
        }
        __syncthreads();

        if (k0 + 32 < K) {
            #pragma unroll
            for (int q = 0; q < 4; ++q) {
                pa[q] = aok ? *(const float4*)(Ap + k0 + 32 + 4*q)
                            : make_float4(0.f,0.f,0.f,0.f);
                pb[q] = *(const float4*)(Bp + (size_t)(k0 + 32) * N + 4*q);
            }
        }

        #pragma unroll
        for (int kk = 0; kk < 4; ++kk) {
            const int kof = kk * 8;
            u32 afr[2][4];
            const int ab = (kof + t4)*132 + warpM + g;
            #pragma unroll
            for (int ma = 0; ma < 2; ++ma) {
                afr[ma][0] = As_t[ab + ma*16];
                afr[ma][1] = As_t[ab + ma*16 + 8];
                afr[ma][2] = As_t[ab + ma*16 + 4*132];
                afr[ma][3] = As_t[ab + ma*16 + 8 + 4*132];
            }
            const int bb = (kof + t4)*132 + warpN + g;
            #pragma unroll
            for (int na = 0; na < 8; ++na) {
                u32 b0 = Bs[bb + na*8];
                u32 b1 = Bs[bb + na*8 + 4*132];
                MMA_TF32(acc[0][na], afr[0], b0, b1);
                MMA_TF32(acc[1][na], afr[1], b0, b1);
            }
        }
    }

    #pragma unroll
    for (int na = 0; na < 8; ++na) {
        const int col = bn * 128 + warpN + na*8 + 2*t4;
        const float2 bv = *(const float2*)&bias[col];
        #pragma unroll
        for (int ma = 0; ma < 2; ++ma) {
            const int r0 = bm * 128 + warpM + ma*16 + g;
            float o0 = acc[ma][na][0] + bv.x;
            float o1 = acc[ma][na][1] + bv.y;
            float o2 = acc[ma][na][2] + bv.x;
            float o3 = acc[ma][na][3] + bv.y;
            if (act) { o0 = tanhf(o0); o1 = tanhf(o1); o2 = tanhf(o2); o3 = tanhf(o3); }
            if (r0 < M)     *(float2*)&C[(size_t)r0 * N + col]       = make_float2(o0, o1);
            if (r0 + 8 < M) *(float2*)&C[(size_t)(r0 + 8) * N + col] = make_float2(o2, o3);
        }
    }
}

// ---------------- persistent bidirectional RNN ---------------------------------
// R3 structure; only change: h staged coalesced into smem (stride 129 float4,
// conflict-free broadcast reads), per-direction release/acquire barrier.
#define RNN_SMEM ((32*516 + 8*516 + 8*288) * 4)

__global__ void __launch_bounds__(256, 1) rnn_kernel(
    const int* __restrict__ length,
    const float* __restrict__ Wf_h, const float* __restrict__ Wb_h)
{
    extern __shared__ float sm[];
    float4* h_s4 = (float4*)sm;               // [b][129 float4] (516 floats/row)
    float*  Whs  = sm + 32 * 516;             // [jl][516]
    float*  red  = Whs + 8 * 516;             // [warp][b*9 + jl]

    const int tid  = threadIdx.x;
    const int wid  = tid >> 5;
    const int lane = tid & 31;
    const int bi   = lane >> 2;
    const int ji   = lane & 3;
    const int dir  = blockIdx.x >> 6;
    const int j0   = (blockIdx.x & 63) * 8;
    const float* W = dir ? Wb_h : Wf_h;
    const float* U = dir ? g_Ub : g_Uf;
    float* hbase   = g_h + dir * 2 * (Bq*Hq);
    unsigned* bar  = &g_bar2[dir * 32];

    const int rb = tid >> 3;
    const int rj = tid & 7;
    const int L  = length[rb];
    float hprev = 0.f;

    for (int i = tid; i < 8 * Hq; i += 256) {
        int kk = i >> 3, jj = i & 7;
        Whs[jj * 516 + kk] = W[kk * Hq + j0 + jj];
    }

    const int kq0 = wid * 16;     // float4 k-offset of this warp's slice
    const int bA  = bi * 4;
    __syncthreads();

    for (int s = 0; s < Tq; ++s) {
        const float4* hin4 = (const float4*)(hbase + (s & 1) * (Bq*Hq));
        float* hout        = hbase + ((s + 1) & 1) * (Bq*Hq);

        // ---- stage h: fully coalesced LDG.128 -> conflict-free smem rows
        #pragma unroll
        for (int it = 0; it < 16; ++it) {
            int f = tid + it * 256;
            h_s4[(f >> 7) * 129 + (f & 127)] = __ldcg(hin4 + f);
        }
        __syncthreads();

        // ---- compute partial dots (reads: 8 distinct rows x 4-lane broadcast)
        u64 acc[4][2];
        #pragma unroll
        for (int ib = 0; ib < 4; ++ib) { acc[ib][0] = 0ull; acc[ib][1] = 0ull; }

        #pragma unroll 8
        for (int it = 0; it < 16; ++it) {
            int kq = kq0 + it;
            int k  = kq * 4;
            float4 h0 = h_s4[(bA + 0) * 129 + kq];
            float4 h1 = h_s4[(bA + 1) * 129 + kq];
            float4 h2 = h_s4[(bA + 2) * 129 + kq];
            float4 h3 = h_s4[(bA + 3) * 129 + kq];
            ulonglong2 wA = *(const ulonglong2*)&Whs[(ji * 2 + 0) * 516 + k];
            ulonglong2 wB = *(const ulonglong2*)&Whs[(ji * 2 + 1) * 516 + k];
            const ulonglong2* hv;
            hv = (const ulonglong2*)&h0;
            fma2(acc[0][0], hv->x, wA.x); fma2(acc[0][0], hv->y, wA.y);
            fma2(acc[0][1], hv->x, wB.x); fma2(acc[0][1], hv->y, wB.y);
            hv = (const ulonglong2*)&h1;
            fma2(acc[1][0], hv->x, wA.x); fma2(acc[1][0], hv->y, wA.y);
            fma2(acc[1][1], hv->x, wB.x); fma2(acc[1][1], hv->y, wB.y);
            hv = (const ulonglong2*)&h2;
            fma2(acc[2][0], hv->x, wA.x); fma2(acc[2][0], hv->y, wA.y);
            fma2(acc[2][1], hv->x, wB.x); fma2(acc[2][1], hv->y, wB.y);
            hv = (const ulonglong2*)&h3;
            fma2(acc[3][0], hv->x, wA.x); fma2(acc[3][0], hv->y, wA.y);
            fma2(acc[3][1], hv->x, wB.x); fma2(acc[3][1], hv->y, wB.y);
        }

        #pragma unroll
        for (int ib = 0; ib < 4; ++ib)
            #pragma unroll
            for (int ij = 0; ij < 2; ++ij) {
                float2 p = upk(acc[ib][ij]);
                red[wid * 288 + (bA + ib) * 9 + (ji * 2 + ij)] = p.x + p.y;
            }
        __syncthreads();

        float dot = 0.f;
        #pragma unroll
        for (int w = 0; w < 8; ++w) dot += red[w * 288 + rb * 9 + rj];

        float hnew;
        if (s < L) {
            int t = dir ? (L - 1 - s) : s;
            float u = U[((size_t)(rb * Tq + t)) * Hq + j0 + rj];
            hnew = tanhf(u + dot);
            g_Z[((size_t)(rb * Tq + t)) * (2*Hq) + dir * Hq + j0 + rj] = hnew;
        } else {
            hnew = hprev;
        }
        hprev = hnew;
        hout[rb * Hq + j0 + rj] = hnew;

        // ---- per-direction grid barrier (release/acquire)
        __syncthreads();
        if (tid == 0) {
            asm volatile("red.release.gpu.global.add.u32 [%0], 1;" :: "l"(bar) : "memory");
            unsigned tgt = (unsigned)(s + 1) * 64u;
            unsigned v;
            do {
                asm volatile("ld.acquire.gpu.u32 %0, [%1];" : "=r"(v) : "l"(bar));
            } while (v < tgt);
        }
        __syncthreads();
    }
}

// ---------------- states assembly ----------------------------------------------
__global__ void states_kernel() {
    int i = blockIdx.x * blockDim.x + threadIdx.x;
    if (i < Bq * 2 * Hq) {
        int b = i >> 10, c = i & 1023;
        int dir = c >> 9, j = c & 511;
        g_S[i] = g_h[dir * 2 * (Bq*Hq) + b * Hq + j];   // final h in pingpong buf 0
    }
}

// ---------------- launcher ------------------------------------------------------
extern "C" void kernel_launch(void* const* d_in, const int* in_sizes, int n_in,
                              void* d_out, int out_size) {
    const float* x      = (const float*)d_in[0];
    const int*   length = (const int*)  d_in[1];
    const float* Wf     = (const float*)d_in[2];
    const float* bf     = (const float*)d_in[3];
    const float* Wb     = (const float*)d_in[4];
    const float* bb     = (const float*)d_in[5];
    const float* W1     = (const float*)d_in[6];
    const float* b1     = (const float*)d_in[7];
    const float* W2     = (const float*)d_in[8];
    const float* b2     = (const float*)d_in[9];
    float* out = (float*)d_out;

    void *pUf, *pUb, *pZ, *pA, *pS, *pAs;
    cudaGetSymbolAddress(&pUf, g_Uf);
    cudaGetSymbolAddress(&pUb, g_Ub);
    cudaGetSymbolAddress(&pZ,  g_Z);
    cudaGetSymbolAddress(&pA,  g_A);
    cudaGetSymbolAddress(&pS,  g_S);
    cudaGetSymbolAddress(&pAs, g_As);

    cudaFuncSetAttribute(rnn_kernel, cudaFuncAttributeMaxDynamicSharedMemorySize, RNN_SMEM);

    const int M = Bq * Tq;   // 16384

    init_kernel<<<2048, 256>>>();

    gemm_tc<<<dim3(Hq/128, M/128), 256>>>(x, Wf, bf, (float*)pUf, M, Hq, Hq, 0);
    gemm_tc<<<dim3(Hq/128, M/128), 256>>>(x, Wb, bb, (float*)pUb, M, Hq, Hq, 0);

    rnn_kernel<<<128, 256, RNN_SMEM>>>(length, Wf + Hq*Hq, Wb + Hq*Hq);

    gemm_tc<<<dim3(FFq/128, M/128), 256>>>((const float*)pZ, W1, b1, (float*)pA, M, FFq, 2*Hq, 1);
    gemm_tc<<<dim3((2*Hq)/128, M/128), 256>>>((const float*)pA, W2, b2, out, M, 2*Hq, FFq, 0);

    states_kernel<<<(Bq*2*Hq + 255)/256, 256>>>();
    gemm_tc<<<dim3(FFq/128, 1), 256>>>((const float*)pS, W1, b1, (float*)pAs, Bq, FFq, 2*Hq, 1);
    gemm_tc<<<dim3((2*Hq)/128, 1), 256>>>((const float*)pAs, W2, b2, out + (size_t)M * 2 * Hq, Bq, 2*Hq, FFq, 0);
}

// round 8
// speedup vs baseline: 2.4129x; 1.0660x over previous
#include <cuda_runtime.h>

#define Bq 32
#define Tq 512
#define Hq 512
#define FFq 2048

typedef unsigned long long u64;
typedef unsigned int u32;

// ---------------- static device scratch ---------------------------------------
__device__ float g_Uf[Bq*Tq*Hq];
__device__ float g_Ub[Bq*Tq*Hq];
__device__ float g_Z [Bq*Tq*2*Hq];
__device__ float g_A [Bq*Tq*FFq];
__device__ float g_h [2*2*Bq*Hq];       // [dir][pingpong][b*H+j]
__device__ float g_S [Bq*2*Hq];
__device__ float g_As[Bq*FFq];
__device__ unsigned g_bar2[64];          // per-dir counters, 128B apart

__device__ __forceinline__ u64 pk2(float lo, float hi) {
    u64 r; asm("mov.b64 %0, {%1, %2};" : "=l"(r) : "f"(lo), "f"(hi)); return r;
}
__device__ __forceinline__ void fma2(u64& d, u64 a, u64 b) {
    asm("fma.rn.f32x2 %0, %1, %2, %0;" : "+l"(d) : "l"(a), "l"(b));
}
__device__ __forceinline__ float2 upk(u64 v) {
    float2 f; asm("mov.b64 {%0, %1}, %2;" : "=f"(f.x), "=f"(f.y) : "l"(v)); return f;
}
__device__ __forceinline__ u32 f2tf32(float f) {
    u32 r; asm("cvt.rna.tf32.f32 %0, %1;" : "=r"(r) : "f"(f)); return r;
}

// ---------------- init ---------------------------------------------------------
__global__ void init_kernel() {
    size_t idx = (size_t)blockIdx.x * blockDim.x + threadIdx.x;
    size_t stride = (size_t)gridDim.x * blockDim.x;
    float4 z = make_float4(0.f, 0.f, 0.f, 0.f);
    for (size_t i = idx; i < (size_t)(Bq*Tq*2*Hq)/4; i += stride) ((float4*)g_Z)[i] = z;
    for (size_t i = idx; i < (size_t)(2*2*Bq*Hq)/4; i += stride) ((float4*)g_h)[i] = z;
    if (idx < 64) g_bar2[idx] = 0u;
}

// ---------------- TF32 tensor-core GEMM: 128x128 tile, k-chunk 32 ---------------
#define MMA_TF32(d, a, b0, b1)                                                  \
    asm volatile("mma.sync.aligned.m16n8k8.row.col.f32.tf32.tf32.f32 "          \
        "{%0,%1,%2,%3}, {%4,%5,%6,%7}, {%8,%9}, {%0,%1,%2,%3};"                 \
        : "+f"(d[0]), "+f"(d[1]), "+f"(d[2]), "+f"(d[3])                        \
        : "r"(a[0]), "r"(a[1]), "r"(a[2]), "r"(a[3]), "r"(b0), "r"(b1))

__global__ void __launch_bounds__(256, 2) gemm_tc(
    const float* __restrict__ A, const float* __restrict__ B,
    const float* __restrict__ bias, float* __restrict__ C,
    int M, int N, int K, int act)
{
    __shared__ u32 As_t[32*132];   // [k][m]
    __shared__ u32 Bs  [32*132];   // [k][n]

    const int tid  = threadIdx.x;
    const int wid  = tid >> 5;
    const int lane = tid & 31;
    const int g    = lane >> 2;
    const int t4   = lane & 3;
    const int bn = blockIdx.x, bm = blockIdx.y;
    const int warpM = (wid & 3) * 32;
    const int warpN = (wid >> 2) * 64;

    float acc[2][8][4];
    #pragma unroll
    for (int ma = 0; ma < 2; ++ma)
        #pragma unroll
        for (int na = 0; na < 8; ++na)
            #pragma unroll
            for (int c = 0; c < 4; ++c) acc[ma][na][c] = 0.f;

    const int arow = tid >> 1;
    const int akb  = (tid & 1) * 16;
    const int brow = tid >> 3;
    const int bcg  = (tid & 7) * 16;
    const int grow = bm * 128 + arow;
    const bool aok = grow < M;
    const float* Ap = A + (size_t)grow * K + akb;
    const float* Bp = B + (size_t)brow * N + bn * 128 + bcg;

    float4 pa[4], pb[4];
    #pragma unroll
    for (int q = 0; q < 4; ++q) {
        pa[q] = aok ? *(const float4*)(Ap + 4*q) : make_float4(0.f,0.f,0.f,0.f);
        pb[q] = *(const float4*)(Bp + 4*q);
    }

    for (int k0 = 0; k0 < K; k0 += 32) {
        __syncthreads();
        #pragma unroll
        for (int q = 0; q < 4; ++q) {
            const float* e = (const float*)&pa[q];
            #pragma unroll
            for (int c = 0; c < 4; ++c)
                As_t[(akb + 4*q + c)*132 + arow] = f2tf32(e[c]);
            const float* f = (const float*)&pb[q];
            #pragma unroll
            for (int c = 0; c < 4; ++c)
                Bs[brow*132 + bcg + 4*q + c] = f2tf32(f[c]);
        }
        __syncthreads();

        if (k0 + 32 < K) {
            #pragma unroll
            for (int q = 0; q < 4; ++q) {
                pa[q] = aok ? *(const float4*)(Ap + k0 + 32 + 4*q)
                            : make_float4(0.f,0.f,0.f,0.f);
                pb[q] = *(const float4*)(Bp + (size_t)(k0 + 32) * N + 4*q);
            }
        }

        #pragma unroll
        for (int kk = 0; kk < 4; ++kk) {
            const int kof = kk * 8;
            u32 afr[2][4];
            const int ab = (kof + t4)*132 + warpM + g;
            #pragma unroll
            for (int ma = 0; ma < 2; ++ma) {
                afr[ma][0] = As_t[ab + ma*16];
                afr[ma][1] = As_t[ab + ma*16 + 8];
                afr[ma][2] = As_t[ab + ma*16 + 4*132];
                afr[ma][3] = As_t[ab + ma*16 + 8 + 4*132];
            }
            const int bb = (kof + t4)*132 + warpN + g;
            #pragma unroll
            for (int na = 0; na < 8; ++na) {
                u32 b0 = Bs[bb + na*8];
                u32 b1 = Bs[bb + na*8 + 4*132];
                MMA_TF32(acc[0][na], afr[0], b0, b1);
                MMA_TF32(acc[1][na], afr[1], b0, b1);
            }
        }
    }

    #pragma unroll
    for (int na = 0; na < 8; ++na) {
        const int col = bn * 128 + warpN + na*8 + 2*t4;
        const float2 bv = *(const float2*)&bias[col];
        #pragma unroll
        for (int ma = 0; ma < 2; ++ma) {
            const int r0 = bm * 128 + warpM + ma*16 + g;
            float o0 = acc[ma][na][0] + bv.x;
            float o1 = acc[ma][na][1] + bv.y;
            float o2 = acc[ma][na][2] + bv.x;
            float o3 = acc[ma][na][3] + bv.y;
            if (act) { o0 = tanhf(o0); o1 = tanhf(o1); o2 = tanhf(o2); o3 = tanhf(o3); }
            if (r0 < M)     *(float2*)&C[(size_t)r0 * N + col]       = make_float2(o0, o1);
            if (r0 + 8 < M) *(float2*)&C[(size_t)(r0 + 8) * N + col] = make_float2(o2, o3);
        }
    }
}

// ---------------- persistent bidirectional RNN ---------------------------------
// h staged into smem with XOR swizzle [b*128 + (c4 ^ ((b>>2)&7))] so the
// 8-row broadcast reads hit 8 distinct banks (conflict-free).
#define RNN_SMEM ((32*512 + 8*516 + 8*288) * 4)

__global__ void __launch_bounds__(256, 1) rnn_kernel(
    const int* __restrict__ length,
    const float* __restrict__ Wf_h, const float* __restrict__ Wb_h)
{
    extern __shared__ float sm[];
    float4* h_s4 = (float4*)sm;               // [b][128 float4], col ^ ((b>>2)&7)
    float*  Whs  = sm + 32 * 512;             // [jl][516]
    float*  red  = Whs + 8 * 516;             // [warp][b*9 + jl]

    const int tid  = threadIdx.x;
    const int wid  = tid >> 5;
    const int lane = tid & 31;
    const int bi   = lane >> 2;
    const int ji   = lane & 3;
    const int dir  = blockIdx.x >> 6;
    const int j0   = (blockIdx.x & 63) * 8;
    const float* W = dir ? Wb_h : Wf_h;
    const float* U = dir ? g_Ub : g_Uf;
    float* hbase   = g_h + dir * 2 * (Bq*Hq);
    unsigned* bar  = &g_bar2[dir * 32];

    const int rb = tid >> 3;
    const int rj = tid & 7;
    const int L  = length[rb];
    float hprev = 0.f;

    for (int i = tid; i < 8 * Hq; i += 256) {
        int kk = i >> 3, jj = i & 7;
        Whs[jj * 516 + kk] = W[kk * Hq + j0 + jj];
    }

    const int kq0 = wid * 16;     // float4 k-offset of this warp's slice
    const int bA  = bi * 4;
    __syncthreads();

    for (int s = 0; s < Tq; ++s) {
        const float4* hin4 = (const float4*)(hbase + (s & 1) * (Bq*Hq));
        float* hout        = hbase + ((s + 1) & 1) * (Bq*Hq);

        // ---- stage h: coalesced LDG.128 -> XOR-swizzled smem (conflict-free)
        #pragma unroll
        for (int it = 0; it < 16; ++it) {
            int f = tid + it * 256;
            int b = f >> 7, c4 = f & 127;
            h_s4[b * 128 + (c4 ^ ((b >> 2) & 7))] = __ldcg(hin4 + f);
        }
        __syncthreads();

        // ---- compute partial dots; read col = kq ^ bi ((bA+ib)>>2 == bi)
        u64 acc[4][2];
        #pragma unroll
        for (int ib = 0; ib < 4; ++ib) { acc[ib][0] = 0ull; acc[ib][1] = 0ull; }

        #pragma unroll 8
        for (int it = 0; it < 16; ++it) {
            int kq = kq0 + it;
            int k  = kq * 4;
            int kc = kq ^ bi;
            float4 h0 = h_s4[(bA + 0) * 128 + kc];
            float4 h1 = h_s4[(bA + 1) * 128 + kc];
            float4 h2 = h_s4[(bA + 2) * 128 + kc];
            float4 h3 = h_s4[(bA + 3) * 128 + kc];
            ulonglong2 wA = *(const ulonglong2*)&Whs[(ji * 2 + 0) * 516 + k];
            ulonglong2 wB = *(const ulonglong2*)&Whs[(ji * 2 + 1) * 516 + k];
            const ulonglong2* hv;
            hv = (const ulonglong2*)&h0;
            fma2(acc[0][0], hv->x, wA.x); fma2(acc[0][0], hv->y, wA.y);
            fma2(acc[0][1], hv->x, wB.x); fma2(acc[0][1], hv->y, wB.y);
            hv = (const ulonglong2*)&h1;
            fma2(acc[1][0], hv->x, wA.x); fma2(acc[1][0], hv->y, wA.y);
            fma2(acc[1][1], hv->x, wB.x); fma2(acc[1][1], hv->y, wB.y);
            hv = (const ulonglong2*)&h2;
            fma2(acc[2][0], hv->x, wA.x); fma2(acc[2][0], hv->y, wA.y);
            fma2(acc[2][1], hv->x, wB.x); fma2(acc[2][1], hv->y, wB.y);
            hv = (const ulonglong2*)&h3;
            fma2(acc[3][0], hv->x, wA.x); fma2(acc[3][0], hv->y, wA.y);
            fma2(acc[3][1], hv->x, wB.x); fma2(acc[3][1], hv->y, wB.y);
        }

        #pragma unroll
        for (int ib = 0; ib < 4; ++ib)
            #pragma unroll
            for (int ij = 0; ij < 2; ++ij) {
                float2 p = upk(acc[ib][ij]);
                red[wid * 288 + (bA + ib) * 9 + (ji * 2 + ij)] = p.x + p.y;
            }
        __syncthreads();

        float dot = 0.f;
        #pragma unroll
        for (int w = 0; w < 8; ++w) dot += red[w * 288 + rb * 9 + rj];

        float hnew;
        if (s < L) {
            int t = dir ? (L - 1 - s) : s;
            float u = U[((size_t)(rb * Tq + t)) * Hq + j0 + rj];
            hnew = tanhf(u + dot);
            g_Z[((size_t)(rb * Tq + t)) * (2*Hq) + dir * Hq + j0 + rj] = hnew;
        } else {
            hnew = hprev;
        }
        hprev = hnew;
        hout[rb * Hq + j0 + rj] = hnew;

        // ---- per-direction grid barrier (release/acquire)
        __syncthreads();
        if (tid == 0) {
            asm volatile("red.release.gpu.global.add.u32 [%0], 1;" :: "l"(bar) : "memory");
            unsigned tgt = (unsigned)(s + 1) * 64u;
            unsigned v;
            do {
                asm volatile("ld.acquire.gpu.u32 %0, [%1];" : "=r"(v) : "l"(bar));
            } while (v < tgt);
        }
        __syncthreads();
    }
}

// ---------------- states assembly ----------------------------------------------
__global__ void states_kernel() {
    int i = blockIdx.x * blockDim.x + threadIdx.x;
    if (i < Bq * 2 * Hq) {
        int b = i >> 10, c = i & 1023;
        int dir = c >> 9, j = c & 511;
        g_S[i] = g_h[dir * 2 * (Bq*Hq) + b * Hq + j];   // final h in pingpong buf 0
    }
}

// ---------------- launcher ------------------------------------------------------
extern "C" void kernel_launch(void* const* d_in, const int* in_sizes, int n_in,
                              void* d_out, int out_size) {
    const float* x      = (const float*)d_in[0];
    const int*   length = (const int*)  d_in[1];
    const float* Wf     = (const float*)d_in[2];
    const float* bf     = (const float*)d_in[3];
    const float* Wb     = (const float*)d_in[4];
    const float* bb     = (const float*)d_in[5];
    const float* W1     = (const float*)d_in[6];
    const float* b1     = (const float*)d_in[7];
    const float* W2     = (const float*)d_in[8];
    const float* b2     = (const float*)d_in[9];
    float* out = (float*)d_out;

    void *pUf, *pUb, *pZ, *pA, *pS, *pAs;
    cudaGetSymbolAddress(&pUf, g_Uf);
    cudaGetSymbolAddress(&pUb, g_Ub);
    cudaGetSymbolAddress(&pZ,  g_Z);
    cudaGetSymbolAddress(&pA,  g_A);
    cudaGetSymbolAddress(&pS,  g_S);
    cudaGetSymbolAddress(&pAs, g_As);

    cudaFuncSetAttribute(rnn_kernel, cudaFuncAttributeMaxDynamicSharedMemorySize, RNN_SMEM);

    const int M = Bq * Tq;   // 16384

    init_kernel<<<2048, 256>>>();

    gemm_tc<<<dim3(Hq/128, M/128), 256>>>(x, Wf, bf, (float*)pUf, M, Hq, Hq, 0);
    gemm_tc<<<dim3(Hq/128, M/128), 256>>>(x, Wb, bb, (float*)pUb, M, Hq, Hq, 0);

    rnn_kernel<<<128, 256, RNN_SMEM>>>(length, Wf + Hq*Hq, Wb + Hq*Hq);

    gemm_tc<<<dim3(FFq/128, M/128), 256>>>((const float*)pZ, W1, b1, (float*)pA, M, FFq, 2*Hq, 1);
    gemm_tc<<<dim3((2*Hq)/128, M/128), 256>>>((const float*)pA, W2, b2, out, M, 2*Hq, FFq, 0);

    states_kernel<<<(Bq*2*Hq + 255)/256, 256>>>();
    gemm_tc<<<dim3(FFq/128, 1), 256>>>((const float*)pS, W1, b1, (float*)pAs, Bq, FFq, 2*Hq, 1);
    gemm_tc<<<dim3((2*Hq)/128, 1), 256>>>((const float*)pAs, W2, b2, out + (size_t)M * 2 * Hq, Bq, 2*Hq, FFq, 0);
}